// round 2
// baseline (speedup 1.0000x reference)
#include <cuda_runtime.h>
#include <cstdint>

#define BATCH 16
#define SEQ   2048
#define DIM   512
#define BD    64
#define NTOK  (BATCH*SEQ)   /* 32768 */
#define NKVQ  192

// ---------------- device scratch (no allocations allowed) ----------------
__device__ float g_Wc[DIM*NKVQ];                 // packed [Wk|Wv|Wq], 512x192
__device__ float g_bc[NKVQ];                     // packed [bk|bv|bq]
__device__ float g_KVQ[(size_t)NTOK*NKVQ];       // per-token k,v,q  (25 MB)
__device__ float g_E[NTOK];                      // per-token eta = sigmoid(x.lr_w + lr_b)
__device__ float g_H[(size_t)NTOK*BD];           // per-token h (scan output, 8.4 MB)

// ---------------- pack kernel ----------------
__global__ void pack_kernel(const float* __restrict__ Wk, const float* __restrict__ Wv,
                            const float* __restrict__ Wq, const float* __restrict__ bk,
                            const float* __restrict__ bv, const float* __restrict__ bq)
{
    int idx = blockIdx.x*256 + threadIdx.x;
    if (idx < DIM*NKVQ){
        int k = idx / NKVQ, n = idx % NKVQ;
        float v;
        if (n < 64)       v = Wk[k*64 + n];
        else if (n < 128) v = Wv[k*64 + (n-64)];
        else              v = Wq[k*64 + (n-128)];
        g_Wc[idx] = v;
    }
    if (idx < NKVQ){
        float v;
        if (idx < 64)       v = bk[idx];
        else if (idx < 128) v = bv[idx-64];
        else                v = bq[idx-128];
        g_bc[idx] = v;
    }
}

// ---------------- fp32 GEMM body: BM=128, BN=64, BK=16, 128 thr, 8x8 tile ----------------
template<int KITERS>
__device__ __forceinline__ void gemm_body(
    const float* __restrict__ A, int lda,
    const float* __restrict__ B, int ldb,
    const float* __restrict__ bias,
    float* __restrict__ C, int ldc)
{
    __shared__ __align__(16) float As[16][128];
    __shared__ __align__(16) float Bs[16][64];

    const int tid = threadIdx.x;
    const int tx  = tid & 7;          // 0..7  col group
    const int ty  = tid >> 3;         // 0..15 row group
    const int mBase = blockIdx.x * 128;
    const int nBase = blockIdx.y * 64;

    const float* Ab = A + (size_t)mBase * lda;
    const float* Bb = B + nBase;

    float acc[8][8];
    #pragma unroll
    for (int i=0;i<8;i++)
        #pragma unroll
        for (int j=0;j<8;j++) acc[i][j] = 0.f;

    const int am  = tid >> 2;   // 0..31
    const int ak4 = tid & 3;    // 0..3

    for (int kt=0; kt<KITERS; kt++){
        const float* Ak = Ab + kt*16;
        const float* Bk = Bb + (size_t)kt*16*ldb;
        #pragma unroll
        for (int p=0;p<4;p++){
            int m = am + 32*p;
            float4 a = *(const float4*)(Ak + (size_t)m*lda + ak4*4);
            As[ak4*4+0][m]=a.x; As[ak4*4+1][m]=a.y; As[ak4*4+2][m]=a.z; As[ak4*4+3][m]=a.w;
        }
        #pragma unroll
        for (int p=0;p<2;p++){
            int id = tid + 128*p;
            int r = id >> 4, c4 = id & 15;
            *(float4*)(&Bs[r][c4*4]) = *(const float4*)(Bk + (size_t)r*ldb + c4*4);
        }
        __syncthreads();
        #pragma unroll
        for (int kk=0; kk<16; kk++){
            float4 a0 = *(const float4*)(&As[kk][ty*8]);
            float4 a1 = *(const float4*)(&As[kk][ty*8+4]);
            float4 b0 = *(const float4*)(&Bs[kk][tx*8]);
            float4 b1 = *(const float4*)(&Bs[kk][tx*8+4]);
            float av[8] = {a0.x,a0.y,a0.z,a0.w,a1.x,a1.y,a1.z,a1.w};
            float bw[8] = {b0.x,b0.y,b0.z,b0.w,b1.x,b1.y,b1.z,b1.w};
            #pragma unroll
            for (int i=0;i<8;i++)
                #pragma unroll
                for (int j=0;j<8;j++)
                    acc[i][j] = fmaf(av[i], bw[j], acc[i][j]);
        }
        __syncthreads();
    }

    float bvc[8];
    #pragma unroll
    for (int j=0;j<8;j++) bvc[j] = bias[nBase + tx*8 + j];
    #pragma unroll
    for (int i=0;i<8;i++){
        int row = mBase + ty*8 + i;
        float4 o0 = make_float4(acc[i][0]+bvc[0], acc[i][1]+bvc[1],
                                acc[i][2]+bvc[2], acc[i][3]+bvc[3]);
        float4 o1 = make_float4(acc[i][4]+bvc[4], acc[i][5]+bvc[5],
                                acc[i][6]+bvc[6], acc[i][7]+bvc[7]);
        *(float4*)(C + (size_t)row*ldc + nBase + tx*8)     = o0;
        *(float4*)(C + (size_t)row*ldc + nBase + tx*8 + 4) = o1;
    }
}

__global__ void __launch_bounds__(128) gemm1_kernel(const float* __restrict__ x){
    gemm_body<32>(x, DIM, g_Wc, NKVQ, g_bc, g_KVQ, NKVQ);
}
__global__ void __launch_bounds__(128) gemm3_kernel(const float* __restrict__ Wo,
                                                    const float* __restrict__ bo,
                                                    float* __restrict__ out){
    gemm_body<4>(g_H, BD, Wo, DIM, bo, out, DIM);
}

// ---------------- eta kernel: one warp per token ----------------
__global__ void eta_kernel(const float* __restrict__ x,
                           const float* __restrict__ lrw,
                           const float* __restrict__ lrb)
{
    int warp = threadIdx.x >> 5, lane = threadIdx.x & 31;
    int row = blockIdx.x*8 + warp;
    const float* xr = x + (size_t)row*DIM;
    float s = 0.f;
    #pragma unroll
    for (int j=0;j<16;j++) s = fmaf(xr[lane + 32*j], lrw[lane + 32*j], s);
    #pragma unroll
    for (int d=16; d; d>>=1) s += __shfl_xor_sync(0xffffffffu, s, d);
    if (lane == 0){
        float raw = s + lrb[0];
        g_E[row] = 1.f/(1.f + expf(-raw));
    }
}

// ---------------- sequential scan: one CTA per batch, W in registers ----------------
// thread t: o = t>>1 owns W row o; half = t&1 owns cols [32*half, 32*half+32)
__global__ void __launch_bounds__(128, 1) scan_kernel(
    const float* __restrict__ W0,
    const float* __restrict__ ln_g,
    const float* __restrict__ ln_b)
{
    __shared__ __align__(16) float sKVQ[2][192];   // [k(64)|v(64)|q(64)]
    __shared__ float sE[2];
    __shared__ float sG[64], sB[64];
    __shared__ __align__(16) float red1[6][4];
    __shared__ __align__(16) float red2[4][4];

    const int tid  = threadIdx.x;
    const int o    = tid >> 1;
    const int half = tid & 1;
    const int cb   = half << 5;
    const int warp = tid >> 5, lane = tid & 31;
    const int b    = blockIdx.x;

    float w[32];
    #pragma unroll
    for (int j=0;j<32;j++) w[j] = W0[o*64 + cb + j];
    if (tid < 64){ sG[tid] = ln_g[tid]; sB[tid] = ln_b[tid]; }

    const float* kvq   = g_KVQ + (size_t)b*SEQ*192;
    const float* ebase = g_E + b*SEQ;
    float*       hbase = g_H + (size_t)b*SEQ*64;

    float4 pre = make_float4(0.f,0.f,0.f,0.f);
    float preE = 0.f;
    if (tid < 48) pre = *(const float4*)(kvq + tid*4);
    if (tid == 0) preE = ebase[0];
    if (tid < 48) *(float4*)(&sKVQ[0][tid*4]) = pre;
    if (tid == 0) sE[0] = preE;
    __syncthreads();

    const float inv = 1.f/64.f;

    for (int t=0; t<SEQ; t++){
        const int p = t & 1;
        // prefetch next token into registers (L2-resident scratch)
        if (t+1 < SEQ){
            if (tid < 48) pre = *(const float4*)(kvq + (size_t)(t+1)*192 + tid*4);
            if (tid == 0) preE = ebase[t+1];
        }
        const float* ks = &sKVQ[p][0];
        const float* vs = &sKVQ[p][64];
        const float* qs = &sKVQ[p][128];

        // two half-matvecs: u = W k, u2 = W q
        float ua=0.f, ub=0.f, ya=0.f, yb=0.f;
        #pragma unroll
        for (int j4=0; j4<8; j4++){
            float4 kk = *(const float4*)(ks + cb + j4*4);
            float4 qq = *(const float4*)(qs + cb + j4*4);
            ua = fmaf(w[j4*4+0], kk.x, ua);
            ub = fmaf(w[j4*4+1], kk.y, ub);
            ua = fmaf(w[j4*4+2], kk.z, ua);
            ub = fmaf(w[j4*4+3], kk.w, ub);
            ya = fmaf(w[j4*4+0], qq.x, ya);
            yb = fmaf(w[j4*4+1], qq.y, yb);
            ya = fmaf(w[j4*4+2], qq.z, ya);
            yb = fmaf(w[j4*4+3], qq.w, yb);
        }
        float up = ua + ub, u2p = ya + yb;
        float u  = up  + __shfl_xor_sync(0xffffffffu, up, 1);
        float u2 = u2p + __shfl_xor_sync(0xffffffffu, u2p, 1);

        float ko = ks[o], vo = vs[o], qo = qs[o];
        float go = sG[o], lb = sB[o];

        // ---- reduction round 1: Su, Suu, Sq, Sqq, Suq, Skq ----
        float t0=u, t1=u*u, t2=u2, t3=u2*u2, t4=u*u2, t5=ko*qo;
        if (half){ t0=0.f;t1=0.f;t2=0.f;t3=0.f;t4=0.f;t5=0.f; }
        #pragma unroll
        for (int d=16; d; d>>=1){
            t0 += __shfl_xor_sync(0xffffffffu,t0,d);
            t1 += __shfl_xor_sync(0xffffffffu,t1,d);
            t2 += __shfl_xor_sync(0xffffffffu,t2,d);
            t3 += __shfl_xor_sync(0xffffffffu,t3,d);
            t4 += __shfl_xor_sync(0xffffffffu,t4,d);
            t5 += __shfl_xor_sync(0xffffffffu,t5,d);
        }
        if (lane == 0){
            red1[0][warp]=t0; red1[1][warp]=t1; red1[2][warp]=t2;
            red1[3][warp]=t3; red1[4][warp]=t4; red1[5][warp]=t5;
        }
        __syncthreads();
        float4 r0 = *(const float4*)red1[0];
        float4 r1 = *(const float4*)red1[1];
        float4 r2 = *(const float4*)red1[2];
        float4 r3 = *(const float4*)red1[3];
        float4 r4 = *(const float4*)red1[4];
        float4 r5 = *(const float4*)red1[5];
        float Su  = (r0.x+r0.y)+(r0.z+r0.w);
        float Suu = (r1.x+r1.y)+(r1.z+r1.w);
        float Sq  = (r2.x+r2.y)+(r2.z+r2.w);
        float Sqq = (r3.x+r3.y)+(r3.z+r3.w);
        float Suq = (r4.x+r4.y)+(r4.z+r4.w);
        float Skq = (r5.x+r5.y)+(r5.z+r5.w);

        float mu   = Su*inv;
        float var  = Suu*inv - mu*mu;
        float rstd = rsqrtf(var + 1e-6f);
        float hat  = (u - mu)*rstd;
        // dL/dhat (LN1 backward input): pred = k + hat*g + b
        float dh   = (2.f*inv)*go*(ko + hat*go + lb - vo);

        // ---- reduction round 2: Sdh, Sdh*u, Su2*dh, Sdh^2 ----
        float s0=dh, s1=dh*u, s2=dh*u2, s3=dh*dh;
        if (half){ s0=0.f;s1=0.f;s2=0.f;s3=0.f; }
        #pragma unroll
        for (int d=16; d; d>>=1){
            s0 += __shfl_xor_sync(0xffffffffu,s0,d);
            s1 += __shfl_xor_sync(0xffffffffu,s1,d);
            s2 += __shfl_xor_sync(0xffffffffu,s2,d);
            s3 += __shfl_xor_sync(0xffffffffu,s3,d);
        }
        if (lane == 0){
            red2[0][warp]=s0; red2[1][warp]=s1; red2[2][warp]=s2; red2[3][warp]=s3;
        }
        __syncthreads();
        float4 q0 = *(const float4*)red2[0];
        float4 q1 = *(const float4*)red2[1];
        float4 q2 = *(const float4*)red2[2];
        float4 q3 = *(const float4*)red2[3];
        float Sdh  = (q0.x+q0.y)+(q0.z+q0.w);
        float Sdhu = (q1.x+q1.y)+(q1.z+q1.w);
        float Sdq  = (q2.x+q2.y)+(q2.z+q2.w);
        float Sdh2 = (q3.x+q3.y)+(q3.z+q3.w);

        float eta = sE[p];
        float m1 = Sdh*inv;
        float m2 = (Sdhu - mu*Sdh)*inv*rstd;          // mean(dh*hat)
        float mean_u2    = Sq*inv;
        float mean_u2sq  = Sqq*inv;
        float mean_u2hat = (Suq - mu*Sq)*inv*rstd;
        float mean_u2dh  = Sdq*inv;
        float mean_u2du  = rstd*(mean_u2dh - m1*mean_u2 - m2*mean_u2hat);
        float R          = var*rstd*rstd;             // var/(var+eps)
        float mean_dh2   = Sdh2*inv;
        float mean_du2   = rstd*rstd*(mean_dh2 - m1*m1 + m2*m2*(R - 2.f));
        float c = eta*Skq;
        // mean(du) == 0 analytically => mean(y) = mean(u2)
        float mean_y = mean_u2;
        float var_y  = mean_u2sq - 2.f*c*mean_u2du + c*c*mean_du2 - mean_y*mean_y;
        float rstdy  = rsqrtf(var_y + 1e-6f);

        float du = rstd*(dh - m1 - hat*m2);
        float y  = u2 - c*du;                         // W_new @ q
        float h  = qo + (y - mean_y)*rstdy*go + lb;
        if (!half) hbase[(size_t)t*64 + o] = h;

        // rank-1 W update: W -= eta * du (x) k
        float coef = eta*du;
        #pragma unroll
        for (int j4=0;j4<8;j4++){
            float4 kk = *(const float4*)(ks + cb + j4*4);
            w[j4*4+0] = fmaf(-coef, kk.x, w[j4*4+0]);
            w[j4*4+1] = fmaf(-coef, kk.y, w[j4*4+1]);
            w[j4*4+2] = fmaf(-coef, kk.z, w[j4*4+2]);
            w[j4*4+3] = fmaf(-coef, kk.w, w[j4*4+3]);
        }

        // stage next token
        if (t+1 < SEQ){
            if (tid < 48) *(float4*)(&sKVQ[p^1][tid*4]) = pre;
            if (tid == 0) sE[p^1] = preE;
        }
        __syncthreads();
    }
}

// ---------------- launch ----------------
extern "C" void kernel_launch(void* const* d_in, const int* in_sizes, int n_in,
                              void* d_out, int out_size)
{
    const float* x   = (const float*)d_in[0];
    const float* Wk  = (const float*)d_in[1];
    const float* bk  = (const float*)d_in[2];
    const float* Wv  = (const float*)d_in[3];
    const float* bv  = (const float*)d_in[4];
    const float* Wq  = (const float*)d_in[5];
    const float* bq  = (const float*)d_in[6];
    const float* Wo  = (const float*)d_in[7];
    const float* bo  = (const float*)d_in[8];
    const float* lng = (const float*)d_in[9];
    const float* lnb = (const float*)d_in[10];
    const float* lrw = (const float*)d_in[11];
    const float* lrb = (const float*)d_in[12];
    const float* W0  = (const float*)d_in[13];
    float* out = (float*)d_out;

    pack_kernel<<<(DIM*NKVQ + 255)/256, 256>>>(Wk, Wv, Wq, bk, bv, bq);
    gemm1_kernel<<<dim3(NTOK/128, 3), 128>>>(x);
    eta_kernel<<<NTOK/8, 256>>>(x, lrw, lrb);
    scan_kernel<<<BATCH, 128>>>(W0, lng, lnb);
    gemm3_kernel<<<dim3(NTOK/128, 8), 128>>>(Wo, bo, out);
}